// round 10
// baseline (speedup 1.0000x reference)
#include <cuda_runtime.h>

#define Bsz 256
#define Tn  100
#define Fn  256
#define Hn  1024
#define On  8
#define NT  512   // scan threads per block

#define ALPHA 0.9048374180359595f   // exp(-0.001/0.01)
#define BETA  0.8187307530779818f   // exp(-0.001/0.005)

// Output layout: out [B,T+1,O], s1 [B,T,H], s2 [B,T,H], v1 [B,T,H], v2 [B,T,H]
#define S1_OFF  (Bsz*(Tn+1)*On)
#define S2_OFF  (S1_OFF + Bsz*Tn*Hn)
#define V1_OFF  (S2_OFF + Bsz*Tn*Hn)
#define V2_OFF  (V1_OFF + Bsz*Tn*Hn)

__device__ float g_H1[(size_t)Bsz * Tn * Hn];   // inputs @ W0
__device__ int   g_flag[Bsz];                   // producer progress per batch

// ---------------------------------------------------------------------------
// fp32 SGEMM, double-buffered smem (1 sync/iter). Sequential-k FFMA chain per
// output element — association identical to reference (bit-exact). (R9.)
// ---------------------------------------------------------------------------
__global__ __launch_bounds__(256) void sgemm_kernel(
    const float* __restrict__ A, const float* __restrict__ B,
    float* __restrict__ C, int M, int N, int K)
{
    __shared__ float As[2][8][128];
    __shared__ float Bs[2][8][128];

    int tid  = threadIdx.x;
    int brow = blockIdx.y * 128;
    int bcol = blockIdx.x * 128;

    int arow = tid >> 1;
    int acol = (tid & 1) << 2;
    int brw  = tid >> 5;
    int bcl  = (tid & 31) << 2;
    int ty = (tid >> 4) << 3;
    int tx = (tid & 15) << 3;

    float acc[8][8];
#pragma unroll
    for (int i = 0; i < 8; i++)
#pragma unroll
        for (int j = 0; j < 8; j++) acc[i][j] = 0.f;

    {
        float4 a4 = *(const float4*)(A + (size_t)(brow + arow) * K + acol);
        As[0][acol + 0][arow] = a4.x;
        As[0][acol + 1][arow] = a4.y;
        As[0][acol + 2][arow] = a4.z;
        As[0][acol + 3][arow] = a4.w;
        *(float4*)&Bs[0][brw][bcl] =
            *(const float4*)(B + (size_t)brw * N + bcol + bcl);
    }
    __syncthreads();

    int p = 0;
    for (int k0 = 0; k0 < K; k0 += 8) {
        bool more = (k0 + 8) < K;
        float4 na, nb;
        if (more) {
            na = *(const float4*)(A + (size_t)(brow + arow) * K + (k0 + 8) + acol);
            nb = *(const float4*)(B + (size_t)(k0 + 8 + brw) * N + bcol + bcl);
        }

#pragma unroll
        for (int kk = 0; kk < 8; kk++) {
            float ar[8], br[8];
#pragma unroll
            for (int i = 0; i < 8; i++) ar[i] = As[p][kk][ty + i];
#pragma unroll
            for (int j = 0; j < 8; j++) br[j] = Bs[p][kk][tx + j];
#pragma unroll
            for (int i = 0; i < 8; i++)
#pragma unroll
                for (int j = 0; j < 8; j++)
                    acc[i][j] = __fmaf_rn(ar[i], br[j], acc[i][j]);
        }

        if (more) {
            int q = p ^ 1;
            As[q][acol + 0][arow] = na.x;
            As[q][acol + 1][arow] = na.y;
            As[q][acol + 2][arow] = na.z;
            As[q][acol + 3][arow] = na.w;
            *(float4*)&Bs[q][brw][bcl] = nb;
        }
        __syncthreads();
        p ^= 1;
    }

#pragma unroll
    for (int i = 0; i < 8; i++) {
        float4 c0 = make_float4(acc[i][0], acc[i][1], acc[i][2], acc[i][3]);
        float4 c1 = make_float4(acc[i][4], acc[i][5], acc[i][6], acc[i][7]);
        *(float4*)(C + (size_t)(brow + ty + i) * N + bcol + tx)     = c0;
        *(float4*)(C + (size_t)(brow + ty + i) * N + bcol + tx + 4) = c1;
    }
}

// ---------------------------------------------------------------------------
// Deterministic compact ascending-index list (R6 exact). Ends synced.
// ---------------------------------------------------------------------------
__device__ __forceinline__ int build_list2(float2 s, int* __restrict__ list,
                                           int* __restrict__ wscan)
{
    int tid  = threadIdx.x;
    int lane = tid & 31;
    int wid  = tid >> 5;

    int idx[2];
    int c = 0;
    int base = tid << 1;
    if (s.x != 0.f) idx[c++] = base;
    if (s.y != 0.f) idx[c++] = base + 1;

    int inc = c;
#pragma unroll
    for (int d = 1; d < 32; d <<= 1) {
        int n = __shfl_up_sync(0xffffffffu, inc, d);
        if (lane >= d) inc += n;
    }
    if (lane == 31) wscan[wid] = inc;
    __syncthreads();
    if (tid == 0) {
        int run = 0;
#pragma unroll
        for (int w = 0; w < 16; w++) { int v = wscan[w]; wscan[w] = run; run += v; }
        wscan[16] = run;
    }
    __syncthreads();
    int start = wscan[wid] + inc - c;
    if (c > 0) list[start] = idx[0];
    if (c > 1) list[start + 1] = idx[1];
    int total = wscan[16];
    __syncthreads();
    return total;
}

#define ACC2(a, r) { (a).x += (r).x; (a).y += (r).y; }
#define ROW2(M, k) (((const float2*)((M) + ((size_t)(k) << 10)))[tid])

// Single gather, sequential ascending order, unroll 8 (bit-exact).
__device__ __forceinline__ float2 gather2(const float* __restrict__ M,
                                          const int* __restrict__ list, int cnt)
{
    int tid = threadIdx.x;
    float2 acc = make_float2(0.f, 0.f);
    int k = 0;
    for (; k + 8 <= cnt; k += 8) {
        float2 r0 = ROW2(M, list[k+0]); float2 r1 = ROW2(M, list[k+1]);
        float2 r2 = ROW2(M, list[k+2]); float2 r3 = ROW2(M, list[k+3]);
        float2 r4 = ROW2(M, list[k+4]); float2 r5 = ROW2(M, list[k+5]);
        float2 r6 = ROW2(M, list[k+6]); float2 r7 = ROW2(M, list[k+7]);
        ACC2(acc, r0); ACC2(acc, r1); ACC2(acc, r2); ACC2(acc, r3);
        ACC2(acc, r4); ACC2(acc, r5); ACC2(acc, r6); ACC2(acc, r7);
    }
    for (; k < cnt; k++) { float2 r = ROW2(M, list[k]); ACC2(acc, r); }
    return acc;
}

// Dual gather: two independent streams interleaved; per-list ascending order.
__device__ __forceinline__ void dual_gather2(
    const float* __restrict__ M0, const int* __restrict__ l0, int c0,
    const float* __restrict__ M1, const int* __restrict__ l1, int c1,
    float2& a0, float2& a1)
{
    int tid = threadIdx.x;
    a0 = make_float2(0.f, 0.f);
    a1 = make_float2(0.f, 0.f);
    int cmin = min(c0, c1);
    int k = 0;
    for (; k + 4 <= cmin; k += 4) {
        float2 p0 = ROW2(M0, l0[k+0]); float2 p1 = ROW2(M0, l0[k+1]);
        float2 p2 = ROW2(M0, l0[k+2]); float2 p3 = ROW2(M0, l0[k+3]);
        float2 q0 = ROW2(M1, l1[k+0]); float2 q1 = ROW2(M1, l1[k+1]);
        float2 q2 = ROW2(M1, l1[k+2]); float2 q3 = ROW2(M1, l1[k+3]);
        ACC2(a0, p0); ACC2(a0, p1); ACC2(a0, p2); ACC2(a0, p3);
        ACC2(a1, q0); ACC2(a1, q1); ACC2(a1, q2); ACC2(a1, q3);
    }
    int k0 = k;
    for (; k0 + 8 <= c0; k0 += 8) {
        float2 r0 = ROW2(M0, l0[k0+0]); float2 r1 = ROW2(M0, l0[k0+1]);
        float2 r2 = ROW2(M0, l0[k0+2]); float2 r3 = ROW2(M0, l0[k0+3]);
        float2 r4 = ROW2(M0, l0[k0+4]); float2 r5 = ROW2(M0, l0[k0+5]);
        float2 r6 = ROW2(M0, l0[k0+6]); float2 r7 = ROW2(M0, l0[k0+7]);
        ACC2(a0, r0); ACC2(a0, r1); ACC2(a0, r2); ACC2(a0, r3);
        ACC2(a0, r4); ACC2(a0, r5); ACC2(a0, r6); ACC2(a0, r7);
    }
    for (; k0 < c0; k0++) { float2 r = ROW2(M0, l0[k0]); ACC2(a0, r); }
    int k1 = k;
    for (; k1 + 8 <= c1; k1 += 8) {
        float2 r0 = ROW2(M1, l1[k1+0]); float2 r1 = ROW2(M1, l1[k1+1]);
        float2 r2 = ROW2(M1, l1[k1+2]); float2 r3 = ROW2(M1, l1[k1+3]);
        float2 r4 = ROW2(M1, l1[k1+4]); float2 r5 = ROW2(M1, l1[k1+5]);
        float2 r6 = ROW2(M1, l1[k1+6]); float2 r7 = ROW2(M1, l1[k1+7]);
        ACC2(a1, r0); ACC2(a1, r1); ACC2(a1, r2); ACC2(a1, r3);
        ACC2(a1, r4); ACC2(a1, r5); ACC2(a1, r6); ACC2(a1, r7);
    }
    for (; k1 < c1; k1++) { float2 r = ROW2(M1, l1[k1]); ACC2(a1, r); }
}

// LIF update, FMA-contracted (bit-exact vs reference).
__device__ __forceinline__ void lif_update(float cur, float pot, float h, float rec,
                                           float& ncur, float& npot, float& spk)
{
    float x = __fadd_rn(pot, -1.0f);
    spk = (x > 0.f) ? 1.f : 0.f;
    float active = __fadd_rn(1.0f, -spk);
    ncur = __fadd_rn(__fmaf_rn(ALPHA, cur, h), rec);
    npot = __fmul_rn(__fmaf_rn(BETA, pot, ncur), active);
}

__device__ __forceinline__ void lif_update2(float2 cur, float2 pot, float2 h, float2 rec,
                                            float2& ncur, float2& npot, float2& spk)
{
    lif_update(cur.x, pot.x, h.x, rec.x, ncur.x, npot.x, spk.x);
    lif_update(cur.y, pot.y, h.y, rec.y, ncur.y, npot.y, spk.y);
}

__global__ void reset_flags_kernel()
{
    g_flag[threadIdx.x] = 0;
}

// ---------------------------------------------------------------------------
// Producer/consumer split scan. Grid = 2*Bsz blocks.
//   bid <  Bsz : PRODUCER (layer 1 for batch bid). Publishes s1[b,t] + flag.
//   bid >= Bsz : CONSUMER (layer 2 + readout for batch bid-Bsz). Spins on flag,
//                reads s1 row, dual-gathers W1/R1.
// Producers never wait -> no deadlock; worst-case scheduling = serialization.
// ---------------------------------------------------------------------------
__global__ __launch_bounds__(NT) void snn_scan_kernel(
    const float* __restrict__ R0, const float* __restrict__ W1,
    const float* __restrict__ R1, const float* __restrict__ Wout,
    float* __restrict__ out,
    float* __restrict__ s1g, float* __restrict__ s2g,
    float* __restrict__ v1g, float* __restrict__ v2g)
{
    __shared__ float sWout[Hn * On];   // consumer only
    __shared__ int   list1[Hn];
    __shared__ int   list2[Hn];        // consumer only
    __shared__ int   wscan[17];
    __shared__ float wsum[16][On];     // consumer only

    int bid  = blockIdx.x;
    int tid  = threadIdx.x;
    int lane = tid & 31;
    int wid  = tid >> 5;
    float2 z = make_float2(0.f, 0.f);

    if (bid < Bsz) {
        // ================= PRODUCER: layer 1 =================
        int b = bid;
        const float* h1base = g_H1 + (size_t)b * Tn * Hn;
        size_t rowbase = (size_t)b * Tn * Hn;

        float2 cur1 = z, pot1 = z, spk1 = z;
        float2 rec1 = z;   // R0 @ spk1[t-1], carried

        for (int t = 0; t < Tn; t++) {
            float2 h1 = ((const float2*)(h1base + (size_t)t * Hn))[tid];
            float2 ncur, npot;
            lif_update2(cur1, pot1, h1, rec1, ncur, npot, spk1);
            cur1 = ncur; pot1 = npot;
            ((float2*)(v1g + rowbase + (size_t)t * Hn))[tid] = pot1;
            ((float2*)(s1g + rowbase + (size_t)t * Hn))[tid] = spk1;

            // Publish: all block stores -> fence -> flag (release pattern).
            __syncthreads();
            if (tid == 0) {
                __threadfence();
                asm volatile("st.global.relaxed.gpu.s32 [%0], %1;"
                             :: "l"(&g_flag[b]), "r"(t + 1) : "memory");
            }

            // Self-gather rec1 for next step (overlaps consumer's work).
            int c1 = build_list2(spk1, list1, wscan);
            rec1 = gather2(R0, list1, c1);
            __syncthreads();   // protect list1 before next build
        }
    } else {
        // ================= CONSUMER: layer 2 + readout =================
        int b = bid - Bsz;
        size_t rowbase = (size_t)b * Tn * Hn;
        __shared__ int s_ready;

#pragma unroll
        for (int i = 0; i < 4; i++)
            ((float4*)sWout)[tid + NT * i] = ((const float4*)Wout)[tid + NT * i];

        if (tid < On) out[(size_t)b * (Tn + 1) * On + tid] = 0.f;

        float2 cur2 = z, pot2 = z, spk2 = z;
        int c2 = 0;
        float cur_ro = 0.f, pot_ro = 0.f;
        __syncthreads();

        for (int t = 0; t < Tn; t++) {
            // Wait for producer to publish s1[b,t].
            if (tid == 0) {
                int v;
                while (true) {
                    asm volatile("ld.acquire.gpu.global.s32 %0, [%1];"
                                 : "=r"(v) : "l"(&g_flag[b]) : "memory");
                    if (v >= t + 1) break;
                    __nanosleep(100);
                }
                s_ready = v;
            }
            __syncthreads();

            // Read s1 row and build list1 (identical ascending order).
            float2 s1row = ((const float2*)(s1g + rowbase + (size_t)t * Hn))[tid];
            int c1 = build_list2(s1row, list1, wscan);

            // Dual gather: h2 = W1@list1, rec2 = R1@list2 (spk2[t-1]).
            float2 h2, rec2;
            dual_gather2(W1, list1, c1, R1, list2, c2, h2, rec2);

            float2 ncur, npot;
            lif_update2(cur2, pot2, h2, rec2, ncur, npot, spk2);
            cur2 = ncur; pot2 = npot;
            ((float2*)(v2g + rowbase + (size_t)t * Hn))[tid] = pot2;
            ((float2*)(s2g + rowbase + (size_t)t * Hn))[tid] = spk2;

            // Readout: h_ro = s2[t] @ Wout, leaky double integrator.
            float pacc[On];
#pragma unroll
            for (int o = 0; o < On; o++) pacc[o] = 0.f;
            int base = tid << 1;
            if (spk2.x != 0.f) {
#pragma unroll
                for (int o = 0; o < On; o++) pacc[o] += sWout[(base + 0) * On + o];
            }
            if (spk2.y != 0.f) {
#pragma unroll
                for (int o = 0; o < On; o++) pacc[o] += sWout[(base + 1) * On + o];
            }
#pragma unroll
            for (int o = 0; o < On; o++) {
                float v = pacc[o];
#pragma unroll
                for (int off = 16; off; off >>= 1)
                    v += __shfl_down_sync(0xffffffffu, v, off);
                if (lane == 0) wsum[wid][o] = v;
            }
            __syncthreads();
            if (tid < On) {
                float tot = 0.f;
#pragma unroll
                for (int w = 0; w < 16; w++) tot += wsum[w][tid];
                cur_ro = __fmaf_rn(ALPHA, cur_ro, tot);
                pot_ro = __fmaf_rn(BETA, pot_ro, cur_ro);
                out[(size_t)b * (Tn + 1) * On + (size_t)(t + 1) * On + tid] = pot_ro;
            }
            __syncthreads();

            // Build list2 from spk2[t] for next step.
            c2 = build_list2(spk2, list2, wscan);
        }
    }
}

extern "C" void kernel_launch(void* const* d_in, const int* in_sizes, int n_in,
                              void* d_out, int out_size)
{
    const float* inputs = (const float*)d_in[0];
    const float* W0     = (const float*)d_in[1];
    const float* W1     = (const float*)d_in[2];
    const float* R0     = (const float*)d_in[3];
    const float* R1     = (const float*)d_in[4];
    const float* Wout   = (const float*)d_in[5];

    float* out = (float*)d_out;
    float* s1 = out + S1_OFF;
    float* s2 = out + S2_OFF;
    float* v1 = out + V1_OFF;
    float* v2 = out + V2_OFF;

    float* h1ptr = nullptr;
    cudaGetSymbolAddress((void**)&h1ptr, g_H1);

    // Reset producer progress flags (required for deterministic graph replay).
    reset_flags_kernel<<<1, Bsz>>>();

    // H1 = inputs @ W0
    {
        dim3 grid(Hn / 128, (Bsz * Tn) / 128);
        sgemm_kernel<<<grid, 256>>>(inputs, W0, h1ptr, Bsz * Tn, Hn, Fn);
    }

    // Producer/consumer split scan: 256 producer blocks + 256 consumer blocks.
    snn_scan_kernel<<<2 * Bsz, NT>>>(R0, W1, R1, Wout, out, s1, s2, v1, v2);
}